// round 13
// baseline (speedup 1.0000x reference)
#include <cuda_runtime.h>
#include <cuda_bf16.h>
#include <math.h>
#include <stdint.h>

#define BB   8
#define NN   2048
#define KNB  32
#define FIN  256
#define FOUT 256
#define CC   512
#define ROWS 16384
#define TM   64

// ---- smem layout (bytes) ----
#define SM_AH   0            // 64 rows x 528B = 33792
#define SM_AL   33792        // -> 67584
#define SM_WH   67584        // 256 n x 48B = 12288 -> 79872
#define SM_WL   79872        // -> 92160
#define SM_BIAS 92160        // 512 f -> 94208
#define SM_IDX  94208        // 64*32*4 -> 102400
#define SM_SQ   102400       // 64 rows x 4 parts x 4B -> 103424
#define SM_TOTAL 103424      // 2 CTAs/SM
#define ASTRB 528            // A row stride bytes -> conflict-free ldmatrix
#define WSTRB 48             // W row stride bytes -> conflict-free ldmatrix

// ---- device scratch ----
__device__ __align__(16) __nv_bfloat16 g_Whi[2 * FOUT * FIN];  // [mat][o][f]
__device__ __align__(16) __nv_bfloat16 g_Wlo[2 * FOUT * FIN];
__device__ float g_invn[ROWS];
__device__ float g_partials[256 * 1024];
__device__ float g_scale[CC];
__device__ float g_shift[CC];

// ---- PTX helpers ----
static __device__ __forceinline__ uint32_t smem_u32(const void* p) {
    uint32_t a;
    asm("{ .reg .u64 t; cvta.to.shared.u64 t, %1; cvt.u32.u64 %0, t; }"
        : "=r"(a) : "l"(p));
    return a;
}
#define LDSM4(r, a) \
    asm volatile("ldmatrix.sync.aligned.m8n8.x4.shared.b16 {%0,%1,%2,%3}, [%4];" \
        : "=r"((r)[0]), "=r"((r)[1]), "=r"((r)[2]), "=r"((r)[3]) : "r"(a))
#define MMA(d, a, b0, b1) \
    asm volatile("mma.sync.aligned.m16n8k16.row.col.f32.bf16.bf16.f32 " \
        "{%0,%1,%2,%3}, {%4,%5,%6,%7}, {%8,%9}, {%0,%1,%2,%3};" \
        : "+f"((d)[0]), "+f"((d)[1]), "+f"((d)[2]), "+f"((d)[3]) \
        : "r"((a)[0]), "r"((a)[1]), "r"((a)[2]), "r"((a)[3]), \
          "r"(b0), "r"(b1))

// ---- float4 -> bf16 hi/lo ----
static __device__ __forceinline__ void cvtsplit(float4 v, uint2& h, uint2& l) {
    __nv_bfloat162 h0 = __floats2bfloat162_rn(v.x, v.y);
    __nv_bfloat162 h1 = __floats2bfloat162_rn(v.z, v.w);
    float2 f0 = __bfloat1622float2(h0);
    float2 f1 = __bfloat1622float2(h1);
    __nv_bfloat162 l0 = __floats2bfloat162_rn(v.x - f0.x, v.y - f0.y);
    __nv_bfloat162 l1 = __floats2bfloat162_rn(v.z - f1.x, v.w - f1.y);
    h = make_uint2(*(uint32_t*)&h0, *(uint32_t*)&h1);
    l = make_uint2(*(uint32_t*)&l0, *(uint32_t*)&l1);
}

// ---------------- k0: split W -> bf16 hi/lo (1/32 folded into Wn) -------------
__global__ void kwsplit(const float* __restrict__ Wx, const float* __restrict__ Wn) {
    int i = blockIdx.x * 256 + threadIdx.x;            // 0..131071
    float v = (i < 65536) ? Wx[i] : Wn[i - 65536] * (1.0f / 32.0f);
    __nv_bfloat16 h = __float2bfloat16(v);
    g_Whi[i] = h;
    g_Wlo[i] = __float2bfloat16(v - __bfloat162float(h));
}

// ---------------- k1: gather + dual GEMM (HMMA) + fused row-norm --------------
// grid (32, 8) = 256 CTAs, 512 threads, 2 CTAs/SM
__global__ __launch_bounds__(512, 2)
void k1_gemm(const float* __restrict__ x,
             const int* __restrict__ idx,
             const float* __restrict__ Wxb, const float* __restrict__ Wnb,
             float* __restrict__ out) {
    extern __shared__ char smem[];
    const uint32_t sb = smem_u32(smem);
    const int tid = threadIdx.x, lane = tid & 31, wid = tid >> 5;  // 16 warps
    const int b = blockIdx.y, n0 = blockIdx.x * TM;
    const float4* Xb = (const float4*)(x + (size_t)b * NN * FIN);

    const int wm = wid >> 2;          // 0..3, 16 rows each
    const int wn = wid & 3;           // 0..3, 64 cols each
    const int g  = lane >> 2, tg = lane & 3;
    float* ssq = (float*)(smem + SM_SQ);

    // ---- bias + idx -> smem ----
    ((float*)(smem + SM_BIAS))[tid] = (tid < 256) ? Wxb[tid] : Wnb[tid - 256];
    int* sIdx = (int*)(smem + SM_IDX);
    for (int i = tid; i < TM * KNB; i += 512) sIdx[i] = idx[n0 * KNB + i];

    // ---- xs -> A tile (bf16 hi/lo) ----
    for (int i = tid; i < TM * 64; i += 512) {
        int r = i >> 6, kq = i & 63;
        uint2 h, l;
        cvtsplit(Xb[(size_t)(n0 + r) * 64 + kq], h, l);
        *(uint2*)(smem + SM_AH + r * ASTRB + kq * 8) = h;
        *(uint2*)(smem + SM_AL + r * ASTRB + kq * 8) = l;
    }
    __syncthreads();

    // fragment addresses
    const uint32_t a_row = (uint32_t)(wm * 16 + (lane & 7) + ((lane >> 3) & 1) * 8);
    const uint32_t a_kb  = (uint32_t)(((lane >> 4) & 1) * 16);
    const uint32_t ah_base = sb + SM_AH + a_row * ASTRB + a_kb;
    const uint32_t al_base = sb + SM_AL + a_row * ASTRB + a_kb;
    // B paired x4: groups (0-7,8-15) -> tile nt, (16-23,24-31) -> tile nt+1
    const uint32_t b_row = (uint32_t)(wn * 64 + (lane & 7) + ((lane >> 4) & 1) * 8);
    const uint32_t b_kb  = (uint32_t)(((lane >> 3) & 1) * 16);
    const uint32_t wh_base = sb + SM_WH + b_row * WSTRB + b_kb;
    const uint32_t wl_base = sb + SM_WL + b_row * WSTRB + b_kb;

#pragma unroll 1
    for (int pass = 0; pass < 2; pass++) {
        float acc[8][4];
#pragma unroll
        for (int nt = 0; nt < 8; nt++)
#pragma unroll
            for (int j = 0; j < 4; j++) acc[nt][j] = 0.f;

        const __nv_bfloat16* WHsrc = g_Whi + pass * 65536;
        const __nv_bfloat16* WLsrc = g_Wlo + pass * 65536;

#pragma unroll 1
        for (int c = 0; c < 16; c++) {          // K chunks of 16
            __syncthreads();
            for (int t = tid; t < 2048; t += 512) {
                int hl = t >> 10, e = t & 1023;
                int n = e >> 2, q = e & 3;
                const __nv_bfloat16* src = hl ? WLsrc : WHsrc;
                uint2 v = *(const uint2*)(src + n * 256 + c * 16 + q * 4);
                *(uint2*)(smem + (hl ? SM_WL : SM_WH) + n * WSTRB + q * 8) = v;
            }
            __syncthreads();

            uint32_t ah[4], al[4];
            LDSM4(ah, ah_base + c * 32);
            LDSM4(al, al_base + c * 32);
#pragma unroll
            for (int ntp = 0; ntp < 4; ntp++) {
                uint32_t bh[4], bl[4];
                LDSM4(bh, wh_base + (uint32_t)(ntp * 16) * WSTRB);
                LDSM4(bl, wl_base + (uint32_t)(ntp * 16) * WSTRB);
                MMA(acc[2 * ntp],     ah, bh[0], bh[1]);
                MMA(acc[2 * ntp],     ah, bl[0], bl[1]);
                MMA(acc[2 * ntp],     al, bh[0], bh[1]);
                MMA(acc[2 * ntp + 1], ah, bh[2], bh[3]);
                MMA(acc[2 * ntp + 1], ah, bl[2], bl[3]);
                MMA(acc[2 * ntp + 1], al, bh[2], bh[3]);
            }
        }

        // ---- epilogue: +bias, write h, accumulate row sumsq ----
        {
            const float* sbias = (const float*)(smem + SM_BIAS) + pass * 256 + wn * 64;
            float* ob = out + ((size_t)b * NN + n0 + wm * 16) * CC
                      + pass * 256 + wn * 64;
            float ss0 = 0.f, ss1 = 0.f;
#pragma unroll
            for (int nt = 0; nt < 8; nt++) {
                int col = nt * 8 + 2 * tg;
                float2 bv = *(const float2*)(sbias + col);
                float2 lo = make_float2(acc[nt][0] + bv.x, acc[nt][1] + bv.y);
                float2 hi = make_float2(acc[nt][2] + bv.x, acc[nt][3] + bv.y);
                ss0 += lo.x * lo.x + lo.y * lo.y;
                ss1 += hi.x * hi.x + hi.y * hi.y;
                *(float2*)(ob + (size_t)g * CC + col)       = lo;
                *(float2*)(ob + (size_t)(g + 8) * CC + col) = hi;
            }
            ss0 += __shfl_xor_sync(0xffffffffu, ss0, 1);
            ss0 += __shfl_xor_sync(0xffffffffu, ss0, 2);
            ss1 += __shfl_xor_sync(0xffffffffu, ss1, 1);
            ss1 += __shfl_xor_sync(0xffffffffu, ss1, 2);
            if (tg == 0) {
                int r0 = wm * 16 + g, r1 = r0 + 8;
                if (pass == 0) {
                    ssq[r0 * 4 + wn] = ss0;
                    ssq[r1 * 4 + wn] = ss1;
                } else {
                    ssq[r0 * 4 + wn] += ss0;
                    ssq[r1 * 4 + wn] += ss1;
                }
            }
        }

        // ---- gather-mean -> A tile (between passes) ----
        if (pass == 0) {
            const int rbase = wid * 4;
            float4 g0[4], g1[4];
#pragma unroll
            for (int rr = 0; rr < 4; rr++) {
                g0[rr] = make_float4(0.f, 0.f, 0.f, 0.f);
                g1[rr] = make_float4(0.f, 0.f, 0.f, 0.f);
            }
            const int* ip = sIdx + rbase * KNB;
#pragma unroll 2
            for (int k = 0; k < KNB; k++) {
#pragma unroll
                for (int rr = 0; rr < 4; rr++) {
                    int nb = ip[rr * KNB + k];
                    const float4* Xr = Xb + (size_t)nb * 64;
                    float4 v0 = Xr[lane];
                    float4 v1 = Xr[lane + 32];
                    g0[rr].x += v0.x; g0[rr].y += v0.y;
                    g0[rr].z += v0.z; g0[rr].w += v0.w;
                    g1[rr].x += v1.x; g1[rr].y += v1.y;
                    g1[rr].z += v1.z; g1[rr].w += v1.w;
                }
            }
            __syncthreads();   // all warps done with pass-0 A reads
#pragma unroll
            for (int rr = 0; rr < 4; rr++) {
                uint2 h, l;
                cvtsplit(g0[rr], h, l);
                *(uint2*)(smem + SM_AH + (rbase + rr) * ASTRB + lane * 8) = h;
                *(uint2*)(smem + SM_AL + (rbase + rr) * ASTRB + lane * 8) = l;
                cvtsplit(g1[rr], h, l);
                *(uint2*)(smem + SM_AH + (rbase + rr) * ASTRB + (lane + 32) * 8) = h;
                *(uint2*)(smem + SM_AL + (rbase + rr) * ASTRB + (lane + 32) * 8) = l;
            }
        }
    }

    // ---- row inverse norms ----
    __syncthreads();
    if (tid < TM) {
        float ss = ssq[tid * 4] + ssq[tid * 4 + 1]
                 + ssq[tid * 4 + 2] + ssq[tid * 4 + 3];
        g_invn[b * NN + n0 + tid] = 1.0f / fmaxf(sqrtf(ss), 1e-12f);
    }
}

// ---------------- k2: channel partials of relu(h * invn)  (read-only h) ------
__global__ __launch_bounds__(256)
void k2_part(const float* __restrict__ h, float* __restrict__ partials) {
    __shared__ float sp[8 * 1024];
    const int tid = threadIdx.x, w = tid >> 5, lane = tid & 31;
    float s1[16], s2[16];
#pragma unroll
    for (int i = 0; i < 16; i++) { s1[i] = 0.f; s2[i] = 0.f; }
    const int row0 = blockIdx.x * 64 + w * 8;
    for (int rr = 0; rr < 8; rr++) {
        const float* hr = h + (size_t)(row0 + rr) * CC;
        float inv = g_invn[row0 + rr];
#pragma unroll
        for (int c = 0; c < 4; c++) {
            float4 v = *(const float4*)(hr + c * 128 + lane * 4);
            float4 t;
            t.x = fmaxf(v.x * inv, 0.f);
            t.y = fmaxf(v.y * inv, 0.f);
            t.z = fmaxf(v.z * inv, 0.f);
            t.w = fmaxf(v.w * inv, 0.f);
            s1[c * 4 + 0] += t.x; s2[c * 4 + 0] += t.x * t.x;
            s1[c * 4 + 1] += t.y; s2[c * 4 + 1] += t.y * t.y;
            s1[c * 4 + 2] += t.z; s2[c * 4 + 2] += t.z * t.z;
            s1[c * 4 + 3] += t.w; s2[c * 4 + 3] += t.w * t.w;
        }
    }
#pragma unroll
    for (int c = 0; c < 4; c++)
#pragma unroll
        for (int j = 0; j < 4; j++) {
            int ch = c * 128 + lane * 4 + j;
            sp[w * 1024 + ch]       = s1[c * 4 + j];
            sp[w * 1024 + 512 + ch] = s2[c * 4 + j];
        }
    __syncthreads();
    for (int i = tid; i < 1024; i += 256) {
        float s = 0.f;
#pragma unroll
        for (int w2 = 0; w2 < 8; w2++) s += sp[w2 * 1024 + i];
        partials[(size_t)blockIdx.x * 1024 + i] = s;
    }
}

// ---------------- k3: partials -> scale/shift (block per channel) -------------
__global__ __launch_bounds__(256)
void k3_stats(const float* __restrict__ partials,
              const float* __restrict__ gamma,
              const float* __restrict__ beta) {
    __shared__ float r1[8], r2[8];
    const int ch = blockIdx.x;              // 0..511
    const int p  = threadIdx.x;             // 0..255 (partial block)
    const int w = p >> 5, lane = p & 31;
    float s1 = partials[(size_t)p * 1024 + ch];
    float s2 = partials[(size_t)p * 1024 + 512 + ch];
#pragma unroll
    for (int o = 16; o; o >>= 1) {
        s1 += __shfl_xor_sync(0xffffffffu, s1, o);
        s2 += __shfl_xor_sync(0xffffffffu, s2, o);
    }
    if (lane == 0) { r1[w] = s1; r2[w] = s2; }
    __syncthreads();
    if (p == 0) {
        float t1 = 0.f, t2 = 0.f;
#pragma unroll
        for (int i = 0; i < 8; i++) { t1 += r1[i]; t2 += r2[i]; }
        const float invN = 1.0f / 16384.0f;
        float mu = t1 * invN;
        float var = t2 * invN - mu * mu;
        float sc = rsqrtf(var + 1e-5f) * gamma[ch];
        g_scale[ch] = sc;
        g_shift[ch] = beta[ch] - mu * sc;
    }
}

// ---------------- k4: apply norm+relu+BN elementwise --------------------------
__global__ __launch_bounds__(256)
void k4_bn(float* __restrict__ h) {
    int i = blockIdx.x * 256 + threadIdx.x;   // float4 index
    int c0 = (i & 127) * 4;
    float inv = g_invn[i >> 7];
    float4 v  = *((float4*)h + i);
    float4 sc = *(const float4*)(g_scale + c0);
    float4 sh = *(const float4*)(g_shift + c0);
    v.x = fmaf(fmaxf(v.x * inv, 0.f), sc.x, sh.x);
    v.y = fmaf(fmaxf(v.y * inv, 0.f), sc.y, sh.y);
    v.z = fmaf(fmaxf(v.z * inv, 0.f), sc.z, sh.z);
    v.w = fmaf(fmaxf(v.w * inv, 0.f), sc.w, sh.w);
    *((float4*)h + i) = v;
}

// ---------------- launch ------------------------------------------------------
extern "C" void kernel_launch(void* const* d_in, const int* in_sizes, int n_in,
                              void* d_out, int out_size) {
    const float* x     = (const float*)d_in[0];
    const int*   idx   = (const int*)d_in[1];
    const float* Wx_w  = (const float*)d_in[2];
    const float* Wx_b  = (const float*)d_in[3];
    const float* Wn_w  = (const float*)d_in[4];
    const float* Wn_b  = (const float*)d_in[5];
    const float* gamma = (const float*)d_in[6];
    const float* beta  = (const float*)d_in[7];
    float* out = (float*)d_out;

    float* parts;
    cudaGetSymbolAddress((void**)&parts, g_partials);

    kwsplit<<<512, 256>>>(Wx_w, Wn_w);

    cudaFuncSetAttribute(k1_gemm, cudaFuncAttributeMaxDynamicSharedMemorySize,
                         SM_TOTAL);
    k1_gemm<<<dim3(NN / TM, BB), 512, SM_TOTAL>>>(x, idx, Wx_b, Wn_b, out);
    k2_part<<<256, 256>>>(out, parts);
    k3_stats<<<512, 256>>>(parts, gamma, beta);
    k4_bn<<<ROWS * CC / 4 / 256, 256>>>(out);
}

// round 15
// speedup vs baseline: 1.2237x; 1.2237x over previous
#include <cuda_runtime.h>
#include <cuda_bf16.h>
#include <math.h>
#include <stdint.h>

#define BB   8
#define NN   2048
#define KNB  32
#define FIN  256
#define FOUT 256
#define CC   512
#define ROWS 16384
#define TM   64

// ---- smem layout (bytes) ----
#define SM_AH   0            // 64 rows x 528B = 33792
#define SM_AL   33792        // -> 67584
#define SM_WH   67584        // 256 n x 48B = 12288 -> 79872
#define SM_WL   79872        // -> 92160
#define SM_BIAS 92160        // 512 f -> 94208
#define SM_IDX  94208        // 64*32*4 -> 102400
#define SM_SQ   102400       // 64 rows x 4 parts x 4B -> 103424
#define SM_ROLE 103424       // 1 int
#define SM_TOTAL 103440      // 2 CTAs/SM
#define ASTRB 528            // A row stride bytes -> conflict-free ldmatrix
#define WSTRB 48             // W row stride bytes -> conflict-free ldmatrix

// ---- device scratch ----
__device__ __align__(16) __nv_bfloat16 g_Whi[2 * FOUT * FIN];  // [mat][o][f]
__device__ __align__(16) __nv_bfloat16 g_Wlo[2 * FOUT * FIN];
__device__ int   g_smctr[256];
__device__ float g_invn[ROWS];
__device__ float g_partials[256 * 1024];
__device__ float g_scale[CC];
__device__ float g_shift[CC];

// ---- PTX helpers ----
static __device__ __forceinline__ uint32_t smem_u32(const void* p) {
    uint32_t a;
    asm("{ .reg .u64 t; cvta.to.shared.u64 t, %1; cvt.u32.u64 %0, t; }"
        : "=r"(a) : "l"(p));
    return a;
}
#define LDSM4(r, a) \
    asm volatile("ldmatrix.sync.aligned.m8n8.x4.shared.b16 {%0,%1,%2,%3}, [%4];" \
        : "=r"((r)[0]), "=r"((r)[1]), "=r"((r)[2]), "=r"((r)[3]) : "r"(a))
#define MMA(d, a, b0, b1) \
    asm volatile("mma.sync.aligned.m16n8k16.row.col.f32.bf16.bf16.f32 " \
        "{%0,%1,%2,%3}, {%4,%5,%6,%7}, {%8,%9}, {%0,%1,%2,%3};" \
        : "+f"((d)[0]), "+f"((d)[1]), "+f"((d)[2]), "+f"((d)[3]) \
        : "r"((a)[0]), "r"((a)[1]), "r"((a)[2]), "r"((a)[3]), \
          "r"(b0), "r"(b1))

// ---- float4 -> bf16 hi/lo ----
static __device__ __forceinline__ void cvtsplit(float4 v, uint2& h, uint2& l) {
    __nv_bfloat162 h0 = __floats2bfloat162_rn(v.x, v.y);
    __nv_bfloat162 h1 = __floats2bfloat162_rn(v.z, v.w);
    float2 f0 = __bfloat1622float2(h0);
    float2 f1 = __bfloat1622float2(h1);
    __nv_bfloat162 l0 = __floats2bfloat162_rn(v.x - f0.x, v.y - f0.y);
    __nv_bfloat162 l1 = __floats2bfloat162_rn(v.z - f1.x, v.w - f1.y);
    h = make_uint2(*(uint32_t*)&h0, *(uint32_t*)&h1);
    l = make_uint2(*(uint32_t*)&l0, *(uint32_t*)&l1);
}

// ---------------- k0: split W -> bf16 hi/lo + zero role counters --------------
__global__ void kwsplit(const float* __restrict__ Wx, const float* __restrict__ Wn) {
    int i = blockIdx.x * 256 + threadIdx.x;            // 0..131071
    if (i < 256) g_smctr[i] = 0;
    float v = (i < 65536) ? Wx[i] : Wn[i - 65536] * (1.0f / 32.0f);
    __nv_bfloat16 h = __float2bfloat16(v);
    g_Whi[i] = h;
    g_Wlo[i] = __float2bfloat16(v - __bfloat162float(h));
}

// ---------------- k1: anti-phased gather + dual GEMM (HMMA) + fused norm ------
// grid (32, 8) = 256 CTAs, 512 threads, 2 CTAs/SM; co-resident CTAs take
// opposite pass orders via per-SM atomic role -> gather overlaps GEMM.
__global__ __launch_bounds__(512, 2)
void k1_gemm(const float* __restrict__ x,
             const int* __restrict__ idx,
             const float* __restrict__ Wxb, const float* __restrict__ Wnb,
             float* __restrict__ out) {
    extern __shared__ char smem[];
    const uint32_t sb = smem_u32(smem);
    const int tid = threadIdx.x, lane = tid & 31, wid = tid >> 5;  // 16 warps
    const int b = blockIdx.y, n0 = blockIdx.x * TM;
    const float4* Xb = (const float4*)(x + (size_t)b * NN * FIN);

    const int wm = wid >> 2;          // 0..3, 16 rows each
    const int wn = wid & 3;           // 0..3, 64 cols each
    const int g  = lane >> 2, tg = lane & 3;
    float* ssq = (float*)(smem + SM_SQ);

    // ---- prologue: bias, idx, ssq zero, role ----
    ((float*)(smem + SM_BIAS))[tid] = (tid < 256) ? Wxb[tid] : Wnb[tid - 256];
    int* sIdx = (int*)(smem + SM_IDX);
    for (int i = tid; i < TM * KNB; i += 512) sIdx[i] = idx[n0 * KNB + i];
    if (tid < 256) ssq[tid] = 0.f;
    if (tid == 0) {
        uint32_t s;
        asm volatile("mov.u32 %0, %%smid;" : "=r"(s));
        *(int*)(smem + SM_ROLE) = atomicAdd(&g_smctr[s & 255], 1) & 1;
    }
    __syncthreads();
    const int rev = *(const int*)(smem + SM_ROLE);

    // fragment addresses
    const uint32_t a_row = (uint32_t)(wm * 16 + (lane & 7) + ((lane >> 3) & 1) * 8);
    const uint32_t a_kb  = (uint32_t)(((lane >> 4) & 1) * 16);
    const uint32_t ah_base = sb + SM_AH + a_row * ASTRB + a_kb;
    const uint32_t al_base = sb + SM_AL + a_row * ASTRB + a_kb;
    const uint32_t b_row = (uint32_t)(wn * 64 + (lane & 7) + ((lane >> 4) & 1) * 8);
    const uint32_t b_kb  = (uint32_t)(((lane >> 3) & 1) * 16);
    const uint32_t wh_base = sb + SM_WH + b_row * WSTRB + b_kb;
    const uint32_t wl_base = sb + SM_WL + b_row * WSTRB + b_kb;

#pragma unroll 1
    for (int step = 0; step < 2; step++) {
        const int pass = rev ? (1 - step) : step;   // 0 = Wx(xs), 1 = Wn(gather)
        if (step == 1) __syncthreads();             // prior pass done reading A

        if (pass == 0) {
            // ---- xs -> A tile (bf16 hi/lo) ----
            for (int i = tid; i < TM * 64; i += 512) {
                int r = i >> 6, kq = i & 63;
                uint2 h, l;
                cvtsplit(Xb[(size_t)(n0 + r) * 64 + kq], h, l);
                *(uint2*)(smem + SM_AH + r * ASTRB + kq * 8) = h;
                *(uint2*)(smem + SM_AL + r * ASTRB + kq * 8) = l;
            }
        } else {
            // ---- gather-mean -> A tile ----
            const int rbase = wid * 4;
            float4 g0[4], g1[4];
#pragma unroll
            for (int rr = 0; rr < 4; rr++) {
                g0[rr] = make_float4(0.f, 0.f, 0.f, 0.f);
                g1[rr] = make_float4(0.f, 0.f, 0.f, 0.f);
            }
            const int* ip = sIdx + rbase * KNB;
#pragma unroll 2
            for (int k = 0; k < KNB; k++) {
#pragma unroll
                for (int rr = 0; rr < 4; rr++) {
                    int nb = ip[rr * KNB + k];
                    const float4* Xr = Xb + (size_t)nb * 64;
                    float4 v0 = Xr[lane];
                    float4 v1 = Xr[lane + 32];
                    g0[rr].x += v0.x; g0[rr].y += v0.y;
                    g0[rr].z += v0.z; g0[rr].w += v0.w;
                    g1[rr].x += v1.x; g1[rr].y += v1.y;
                    g1[rr].z += v1.z; g1[rr].w += v1.w;
                }
            }
#pragma unroll
            for (int rr = 0; rr < 4; rr++) {
                uint2 h, l;
                cvtsplit(g0[rr], h, l);
                *(uint2*)(smem + SM_AH + (rbase + rr) * ASTRB + lane * 8) = h;
                *(uint2*)(smem + SM_AL + (rbase + rr) * ASTRB + lane * 8) = l;
                cvtsplit(g1[rr], h, l);
                *(uint2*)(smem + SM_AH + (rbase + rr) * ASTRB + (lane + 32) * 8) = h;
                *(uint2*)(smem + SM_AL + (rbase + rr) * ASTRB + (lane + 32) * 8) = l;
            }
        }

        // ---- GEMM pass ----
        float acc[8][4];
#pragma unroll
        for (int nt = 0; nt < 8; nt++)
#pragma unroll
            for (int j = 0; j < 4; j++) acc[nt][j] = 0.f;

        const __nv_bfloat16* WHsrc = g_Whi + pass * 65536;
        const __nv_bfloat16* WLsrc = g_Wlo + pass * 65536;

#pragma unroll 1
        for (int c = 0; c < 16; c++) {          // K chunks of 16
            __syncthreads();                    // also publishes A-tile stores
            for (int t = tid; t < 2048; t += 512) {
                int hl = t >> 10, e = t & 1023;
                int n = e >> 2, q = e & 3;
                const __nv_bfloat16* src = hl ? WLsrc : WHsrc;
                uint2 v = *(const uint2*)(src + n * 256 + c * 16 + q * 4);
                *(uint2*)(smem + (hl ? SM_WL : SM_WH) + n * WSTRB + q * 8) = v;
            }
            __syncthreads();

            uint32_t ah[4], al[4];
            LDSM4(ah, ah_base + c * 32);
            LDSM4(al, al_base + c * 32);
#pragma unroll
            for (int ntp = 0; ntp < 4; ntp++) {
                uint32_t bh[4], bl[4];
                LDSM4(bh, wh_base + (uint32_t)(ntp * 16) * WSTRB);
                LDSM4(bl, wl_base + (uint32_t)(ntp * 16) * WSTRB);
                MMA(acc[2 * ntp],     ah, bh[0], bh[1]);
                MMA(acc[2 * ntp],     ah, bl[0], bl[1]);
                MMA(acc[2 * ntp],     al, bh[0], bh[1]);
                MMA(acc[2 * ntp + 1], ah, bh[2], bh[3]);
                MMA(acc[2 * ntp + 1], ah, bl[2], bl[3]);
                MMA(acc[2 * ntp + 1], al, bh[2], bh[3]);
            }
        }

        // ---- epilogue: +bias, write h, accumulate row sumsq ----
        {
            const float* sbias = (const float*)(smem + SM_BIAS) + pass * 256 + wn * 64;
            float* ob = out + ((size_t)b * NN + n0 + wm * 16) * CC
                      + pass * 256 + wn * 64;
            float ss0 = 0.f, ss1 = 0.f;
#pragma unroll
            for (int nt = 0; nt < 8; nt++) {
                int col = nt * 8 + 2 * tg;
                float2 bv = *(const float2*)(sbias + col);
                float2 lo = make_float2(acc[nt][0] + bv.x, acc[nt][1] + bv.y);
                float2 hi = make_float2(acc[nt][2] + bv.x, acc[nt][3] + bv.y);
                ss0 += lo.x * lo.x + lo.y * lo.y;
                ss1 += hi.x * hi.x + hi.y * hi.y;
                *(float2*)(ob + (size_t)g * CC + col)       = lo;
                *(float2*)(ob + (size_t)(g + 8) * CC + col) = hi;
            }
            ss0 += __shfl_xor_sync(0xffffffffu, ss0, 1);
            ss0 += __shfl_xor_sync(0xffffffffu, ss0, 2);
            ss1 += __shfl_xor_sync(0xffffffffu, ss1, 1);
            ss1 += __shfl_xor_sync(0xffffffffu, ss1, 2);
            if (tg == 0) {
                int r0 = wm * 16 + g, r1 = r0 + 8;
                ssq[r0 * 4 + wn] += ss0;
                ssq[r1 * 4 + wn] += ss1;
            }
        }
    }

    // ---- row inverse norms ----
    __syncthreads();
    if (tid < TM) {
        float ss = ssq[tid * 4] + ssq[tid * 4 + 1]
                 + ssq[tid * 4 + 2] + ssq[tid * 4 + 3];
        g_invn[b * NN + n0 + tid] = 1.0f / fmaxf(sqrtf(ss), 1e-12f);
    }
}

// ---------------- k2: channel partials of relu(h * invn)  (read-only h) ------
__global__ __launch_bounds__(256)
void k2_part(const float* __restrict__ h, float* __restrict__ partials) {
    __shared__ float sp[8 * 1024];
    const int tid = threadIdx.x, w = tid >> 5, lane = tid & 31;
    float s1[16], s2[16];
#pragma unroll
    for (int i = 0; i < 16; i++) { s1[i] = 0.f; s2[i] = 0.f; }
    const int row0 = blockIdx.x * 64 + w * 8;
    for (int rr = 0; rr < 8; rr++) {
        const float* hr = h + (size_t)(row0 + rr) * CC;
        float inv = g_invn[row0 + rr];
#pragma unroll
        for (int c = 0; c < 4; c++) {
            float4 v = *(const float4*)(hr + c * 128 + lane * 4);
            float4 t;
            t.x = fmaxf(v.x * inv, 0.f);
            t.y = fmaxf(v.y * inv, 0.f);
            t.z = fmaxf(v.z * inv, 0.f);
            t.w = fmaxf(v.w * inv, 0.f);
            s1[c * 4 + 0] += t.x; s2[c * 4 + 0] += t.x * t.x;
            s1[c * 4 + 1] += t.y; s2[c * 4 + 1] += t.y * t.y;
            s1[c * 4 + 2] += t.z; s2[c * 4 + 2] += t.z * t.z;
            s1[c * 4 + 3] += t.w; s2[c * 4 + 3] += t.w * t.w;
        }
    }
#pragma unroll
    for (int c = 0; c < 4; c++)
#pragma unroll
        for (int j = 0; j < 4; j++) {
            int ch = c * 128 + lane * 4 + j;
            sp[w * 1024 + ch]       = s1[c * 4 + j];
            sp[w * 1024 + 512 + ch] = s2[c * 4 + j];
        }
    __syncthreads();
    for (int i = tid; i < 1024; i += 256) {
        float s = 0.f;
#pragma unroll
        for (int w2 = 0; w2 < 8; w2++) s += sp[w2 * 1024 + i];
        partials[(size_t)blockIdx.x * 1024 + i] = s;
    }
}

// ---------------- k3: partials -> scale/shift (block per channel) -------------
__global__ __launch_bounds__(256)
void k3_stats(const float* __restrict__ partials,
              const float* __restrict__ gamma,
              const float* __restrict__ beta) {
    __shared__ float r1[8], r2[8];
    const int ch = blockIdx.x;              // 0..511
    const int p  = threadIdx.x;             // 0..255 (partial block)
    const int w = p >> 5, lane = p & 31;
    float s1 = partials[(size_t)p * 1024 + ch];
    float s2 = partials[(size_t)p * 1024 + 512 + ch];
#pragma unroll
    for (int o = 16; o; o >>= 1) {
        s1 += __shfl_xor_sync(0xffffffffu, s1, o);
        s2 += __shfl_xor_sync(0xffffffffu, s2, o);
    }
    if (lane == 0) { r1[w] = s1; r2[w] = s2; }
    __syncthreads();
    if (p == 0) {
        float t1 = 0.f, t2 = 0.f;
#pragma unroll
        for (int i = 0; i < 8; i++) { t1 += r1[i]; t2 += r2[i]; }
        const float invN = 1.0f / 16384.0f;
        float mu = t1 * invN;
        float var = t2 * invN - mu * mu;
        float sc = rsqrtf(var + 1e-5f) * gamma[ch];
        g_scale[ch] = sc;
        g_shift[ch] = beta[ch] - mu * sc;
    }
}

// ---------------- k4: apply norm+relu+BN elementwise --------------------------
__global__ __launch_bounds__(256)
void k4_bn(float* __restrict__ h) {
    int i = blockIdx.x * 256 + threadIdx.x;   // float4 index
    int c0 = (i & 127) * 4;
    float inv = g_invn[i >> 7];
    float4 v  = *((float4*)h + i);
    float4 sc = *(const float4*)(g_scale + c0);
    float4 sh = *(const float4*)(g_shift + c0);
    v.x = fmaf(fmaxf(v.x * inv, 0.f), sc.x, sh.x);
    v.y = fmaf(fmaxf(v.y * inv, 0.f), sc.y, sh.y);
    v.z = fmaf(fmaxf(v.z * inv, 0.f), sc.z, sh.z);
    v.w = fmaf(fmaxf(v.w * inv, 0.f), sc.w, sh.w);
    *((float4*)h + i) = v;
}

// ---------------- launch ------------------------------------------------------
extern "C" void kernel_launch(void* const* d_in, const int* in_sizes, int n_in,
                              void* d_out, int out_size) {
    const float* x     = (const float*)d_in[0];
    const int*   idx   = (const int*)d_in[1];
    const float* Wx_w  = (const float*)d_in[2];
    const float* Wx_b  = (const float*)d_in[3];
    const float* Wn_w  = (const float*)d_in[4];
    const float* Wn_b  = (const float*)d_in[5];
    const float* gamma = (const float*)d_in[6];
    const float* beta  = (const float*)d_in[7];
    float* out = (float*)d_out;

    float* parts;
    cudaGetSymbolAddress((void**)&parts, g_partials);

    kwsplit<<<512, 256>>>(Wx_w, Wn_w);

    cudaFuncSetAttribute(k1_gemm, cudaFuncAttributeMaxDynamicSharedMemorySize,
                         SM_TOTAL);
    k1_gemm<<<dim3(NN / TM, BB), 512, SM_TOTAL>>>(x, idx, Wx_b, Wn_b, out);
    k2_part<<<256, 256>>>(out, parts);
    k3_stats<<<512, 256>>>(parts, gamma, beta);
    k4_bn<<<ROWS * CC / 4 / 256, 256>>>(out);
}